// round 1
// baseline (speedup 1.0000x reference)
#include <cuda_runtime.h>
#include <cstdint>
#include <math.h>

#define NB 128   // batch
#define NS 100   // seq len
#define NM 50    // memory slots
#define ND 128   // dim
#define T  256   // threads per CTA (recurrent kernel)

// Scratch for precomputed attention weights and qe@W1b+b1
__device__ float g_attn[NB * NS * NM];
__device__ float g_q1[NB * NS * ND];

// ---------------------------------------------------------------------------
// K1: per (b, s-chunk): gather q_emb, attention softmax, q1 = qe@W1b + b1
// grid (NB, 4), 256 threads; each block handles 25 sequence positions.
// ---------------------------------------------------------------------------
__global__ void precompute_kernel(const int* __restrict__ qseq,
                                  const float* __restrict__ emb,
                                  const float* __restrict__ keym,
                                  const float* __restrict__ vu_w1,
                                  const float* __restrict__ vu_b1) {
    __shared__ float sQe[ND];
    __shared__ float sPart[8 * ND];
    __shared__ float sLog[NM];
    const int b = blockIdx.x;
    const int t = threadIdx.x;
    const float* w1b = vu_w1 + ND * ND;   // rows 128..255 of vu_w1
    const int s0 = blockIdx.y * 25;

    for (int si = 0; si < 25; si++) {
        const int s = s0 + si;
        const int qi = qseq[b * NS + s];
        if (t < ND) sQe[t] = emb[qi * ND + t];
        __syncthreads();

        // attention logits: thread t<200: m = t/4, quarter = t%4 (32 d each)
        if (t < 4 * NM) {
            const int m = t >> 2, qd = t & 3;
            const float* kr = keym + m * ND + qd * 32;
            const float* qe = sQe + qd * 32;
            float acc = 0.f;
#pragma unroll
            for (int i = 0; i < 32; i++) acc = fmaf(kr[i], qe[i], acc);
            sPart[t] = acc;
        }
        __syncthreads();
        if (t < NM)
            sLog[t] = sPart[t * 4] + sPart[t * 4 + 1] + sPart[t * 4 + 2] + sPart[t * 4 + 3];
        __syncthreads();

        // softmax over M=50 by warp 0
        if (t < 32) {
            float mx = -1e30f;
            mx = fmaxf(mx, sLog[t]);
            if (t + 32 < NM) mx = fmaxf(mx, sLog[t + 32]);
#pragma unroll
            for (int o = 16; o; o >>= 1) mx = fmaxf(mx, __shfl_xor_sync(0xffffffffu, mx, o));
            float e0 = __expf(sLog[t] - mx);
            float e1 = (t + 32 < NM) ? __expf(sLog[t + 32] - mx) : 0.f;
            float sum = e0 + e1;
#pragma unroll
            for (int o = 16; o; o >>= 1) sum += __shfl_xor_sync(0xffffffffu, sum, o);
            const float inv = 1.f / sum;
            g_attn[(b * NS + s) * NM + t] = e0 * inv;
            if (t + 32 < NM) g_attn[(b * NS + s) * NM + t + 32] = e1 * inv;
        }

        // q1[j] = sum_k qe[k] * w1b[k][j]  (all 256 threads)
        {
            const int j4 = (t & 31) * 4, kg = t >> 5;
            float4 acc = {0.f, 0.f, 0.f, 0.f};
#pragma unroll
            for (int i = 0; i < 16; i++) {
                const int k = kg * 16 + i;
                const float x = sQe[k];
                const float4 w = *(const float4*)(w1b + k * ND + j4);
                acc.x = fmaf(x, w.x, acc.x);
                acc.y = fmaf(x, w.y, acc.y);
                acc.z = fmaf(x, w.z, acc.z);
                acc.w = fmaf(x, w.w, acc.w);
            }
            *(float4*)(sPart + kg * ND + j4) = acc;
        }
        __syncthreads();
        if (t < ND) {
            float v = vu_b1[t];
#pragma unroll
            for (int g = 0; g < 8; g++) v += sPart[g * ND + t];
            g_q1[(b * NS + s) * ND + t] = v;
        }
        __syncthreads();
    }
}

// ---------------------------------------------------------------------------
// K2: persistent recurrent kernel — one CTA per batch element.
// W1a, W2 in smem (fp32); [er_w | ad_w] in registers (128 fp32/thread);
// v state in smem; the v update is fused with the NEXT step's read.
// ---------------------------------------------------------------------------
// smem layout (in floats)
#define SM_W1   0
#define SM_W2   16384
#define SM_V    32768          // 50*128
#define SM_ATTN 39168          // 100*50
#define SM_P    44168          // 4*256 reduction scratch
#define SM_READ 45192
#define SM_H    45320
#define SM_UP   45448
#define SM_E    45576
#define SM_A    45704
#define SM_TOTF 45832
#define SMEM_BYTES (SM_TOTF * 4)

__global__ __launch_bounds__(T, 1)
void recurrent_kernel(const int* __restrict__ qseq,
                      const float* __restrict__ emb,
                      const float* __restrict__ vu_w1,
                      const float* __restrict__ vu_w2,
                      const float* __restrict__ vu_b2,
                      const float* __restrict__ er_w,
                      const float* __restrict__ er_b,
                      const float* __restrict__ ad_w,
                      const float* __restrict__ ad_b,
                      const float* __restrict__ out_w1,
                      const float* __restrict__ out_b1,
                      const float* __restrict__ out_w2,
                      const float* __restrict__ out_b2,
                      float* __restrict__ out) {
    extern __shared__ float sm[];
    float* sW1   = sm + SM_W1;
    float* sW2   = sm + SM_W2;
    float* sV    = sm + SM_V;
    float* sAttn = sm + SM_ATTN;
    float* sP    = sm + SM_P;
    float* sRead = sm + SM_READ;
    float* sH    = sm + SM_H;
    float* sUp   = sm + SM_UP;
    float* sE    = sm + SM_E;
    float* sA    = sm + SM_A;

    const int b = blockIdx.x;
    const int t = threadIdx.x;

    // ---- load weights / init state ----
    for (int i = t; i < ND * ND; i += T) { sW1[i] = vu_w1[i]; sW2[i] = vu_w2[i]; }
    for (int i = t; i < NM * ND; i += T) sV[i] = 0.f;
    for (int i = t; i < NS * NM; i += T) sAttn[i] = g_attn[b * NS * NM + i];
    if (t < ND) sRead[t] = 0.f;

    // [er_w | ad_w] into registers: thread owns 4 outputs (jq) x 32 k (ks)
    const int jq = t & 63;       // output quad index over 256 combined outputs
    const int ks = t >> 6;       // k slice (4 slices of 32)
    float ea[128];
    {
        const float* src = (jq < 32) ? (er_w + jq * 4) : (ad_w + (jq - 32) * 4);
#pragma unroll
        for (int kk = 0; kk < 32; kk++) {
            const float4 w4 = *(const float4*)(src + (ks * 32 + kk) * ND);
            ea[kk * 4 + 0] = w4.x; ea[kk * 4 + 1] = w4.y;
            ea[kk * 4 + 2] = w4.z; ea[kk * 4 + 3] = w4.w;
        }
    }
    const float biasO = (t < ND) ? er_b[t] : ad_b[t - ND];  // for C reduce, output t
    const float b2r   = (t < ND) ? vu_b2[t] : 0.f;

    // stage mappings
    const int j4 = (t & 31) * 4;   // GEMV1/2: 4 adjacent outputs
    const int kg = t >> 5;         // GEMV1/2: 8 k-groups of 16 (== warp id)
    const int d2 = t & 63;         // D stage: d pair
    const int mg = t >> 6;         // D stage: 4 m-groups
    const int mstart = (mg < 2) ? mg * 13 : 26 + (mg - 2) * 12;
    const int mcount = (mg < 2) ? 13 : 12;

    __syncthreads();

    const float* q1b = g_q1 + b * NS * ND;

    for (int s = 0; s < NS; s++) {
        // prefetch this step's q1 (consumed in A-reduce)
        float q1v = 0.f;
        if (t < ND) q1v = q1b[s * ND + t];

        // ---- A: h = tanh(read @ W1a + q1) ----
        {
            float4 acc = {0.f, 0.f, 0.f, 0.f};
#pragma unroll
            for (int i = 0; i < 16; i++) {
                const int k = kg * 16 + i;
                const float x = sRead[k];
                const float4 w = *(const float4*)(sW1 + k * ND + j4);
                acc.x = fmaf(x, w.x, acc.x);
                acc.y = fmaf(x, w.y, acc.y);
                acc.z = fmaf(x, w.z, acc.z);
                acc.w = fmaf(x, w.w, acc.w);
            }
            *(float4*)(sP + kg * ND + j4) = acc;
        }
        __syncthreads();
        if (t < ND) {
            float v = q1v;
#pragma unroll
            for (int g = 0; g < 8; g++) v += sP[g * ND + t];
            sH[t] = tanhf(v);
        }
        __syncthreads();

        // ---- B: up = h @ W2 + b2 ----
        {
            float4 acc = {0.f, 0.f, 0.f, 0.f};
#pragma unroll
            for (int i = 0; i < 16; i++) {
                const int k = kg * 16 + i;
                const float x = sH[k];
                const float4 w = *(const float4*)(sW2 + k * ND + j4);
                acc.x = fmaf(x, w.x, acc.x);
                acc.y = fmaf(x, w.y, acc.y);
                acc.z = fmaf(x, w.z, acc.z);
                acc.w = fmaf(x, w.w, acc.w);
            }
            *(float4*)(sP + kg * ND + j4) = acc;
        }
        __syncthreads();
        if (t < ND) {
            float v = b2r;
#pragma unroll
            for (int g = 0; g < 8; g++) v += sP[g * ND + t];
            sUp[t] = v;
        }
        __syncthreads();

        // ---- C: e = sigmoid(up@er_w + er_b), a = tanh(up@ad_w + ad_b) (regs) ----
        {
            float4 acc = {0.f, 0.f, 0.f, 0.f};
#pragma unroll
            for (int kk = 0; kk < 32; kk++) {
                const float x = sUp[ks * 32 + kk];
                acc.x = fmaf(x, ea[kk * 4 + 0], acc.x);
                acc.y = fmaf(x, ea[kk * 4 + 1], acc.y);
                acc.z = fmaf(x, ea[kk * 4 + 2], acc.z);
                acc.w = fmaf(x, ea[kk * 4 + 3], acc.w);
            }
            *(float4*)(sP + ks * 256 + jq * 4) = acc;
        }
        __syncthreads();
        {
            float v = biasO;
#pragma unroll
            for (int g = 0; g < 4; g++) v += sP[g * 256 + t];
            if (t < ND) sE[t] = 1.f / (1.f + __expf(-v));
            else        sA[t - ND] = tanhf(v);
        }
        __syncthreads();

        // ---- D: v <- v + w_t*(a - e*v), fused with next read = w_{t+1} . v ----
        {
            const float* wrow = sAttn + s * NM;
            const float* wnxt = sAttn + ((s + 1 < NS) ? s + 1 : NS - 1) * NM;
            const float ex = sE[d2 * 2], ey = sE[d2 * 2 + 1];
            const float ax = sA[d2 * 2], ay = sA[d2 * 2 + 1];
            float rpx = 0.f, rpy = 0.f;
#pragma unroll
            for (int mi = 0; mi < 13; mi++) {
                if (mi < mcount) {
                    const int m = mstart + mi;
                    const float wt = wrow[m];
                    const float wn = wnxt[m];
                    float2 v2 = *(float2*)(sV + m * ND + d2 * 2);
                    const float fx = fmaf(-ex, v2.x, ax);
                    const float fy = fmaf(-ey, v2.y, ay);
                    v2.x = fmaf(wt, fx, v2.x);
                    v2.y = fmaf(wt, fy, v2.y);
                    *(float2*)(sV + m * ND + d2 * 2) = v2;
                    rpx = fmaf(wn, v2.x, rpx);
                    rpy = fmaf(wn, v2.y, rpy);
                }
            }
            sP[mg * ND + d2 * 2]     = rpx;
            sP[mg * ND + d2 * 2 + 1] = rpy;
        }
        __syncthreads();
        if (t < ND) {
            float v = 0.f;
#pragma unroll
            for (int g = 0; g < 4; g++) v += sP[g * ND + t];
            sRead[t] = v;
        }
        __syncthreads();
    }

    // ---- output head: pred = sigmoid(relu([read, qe_last] @ out_w1 + b1) @ out_w2 + b2)
    {
        const int qi = qseq[b * NS + (NS - 1)];
        if (t < ND) sUp[t] = emb[qi * ND + t];   // qe_last
    }
    __syncthreads();
    {
        // 256-k GEMV: kg in 0..7 owns 32 k; k<128 from sRead, k>=128 from sUp
        const float* pin = (kg < 4) ? sRead : (sUp - ND);
        float4 acc = {0.f, 0.f, 0.f, 0.f};
#pragma unroll
        for (int i = 0; i < 32; i++) {
            const int k = kg * 32 + i;
            const float x = pin[k];
            const float4 w = *(const float4*)(out_w1 + k * ND + j4);
            acc.x = fmaf(x, w.x, acc.x);
            acc.y = fmaf(x, w.y, acc.y);
            acc.z = fmaf(x, w.z, acc.z);
            acc.w = fmaf(x, w.w, acc.w);
        }
        *(float4*)(sP + kg * ND + j4) = acc;
    }
    __syncthreads();
    if (t < ND) {
        float v = out_b1[t];
#pragma unroll
        for (int g = 0; g < 8; g++) v += sP[g * ND + t];
        sH[t] = fmaxf(v, 0.f) * out_w2[t];
    }
    __syncthreads();
    if (t < 32) {
        float v = sH[t] + sH[t + 32] + sH[t + 64] + sH[t + 96];
#pragma unroll
        for (int o = 16; o; o >>= 1) v += __shfl_xor_sync(0xffffffffu, v, o);
        if (t == 0) out[b] = 1.f / (1.f + __expf(-(v + out_b2[0])));
    }
}

// ---------------------------------------------------------------------------
extern "C" void kernel_launch(void* const* d_in, const int* in_sizes, int n_in,
                              void* d_out, int out_size) {
    const int*   qseq   = (const int*)  d_in[0];
    // d_in[1] = answer_seq (unused by reference)
    const float* emb    = (const float*)d_in[2];
    const float* keym   = (const float*)d_in[3];
    const float* vu_w1  = (const float*)d_in[4];
    const float* vu_b1  = (const float*)d_in[5];
    const float* vu_w2  = (const float*)d_in[6];
    const float* vu_b2  = (const float*)d_in[7];
    const float* er_w   = (const float*)d_in[8];
    const float* er_b   = (const float*)d_in[9];
    const float* ad_w   = (const float*)d_in[10];
    const float* ad_b   = (const float*)d_in[11];
    const float* out_w1 = (const float*)d_in[12];
    const float* out_b1 = (const float*)d_in[13];
    const float* out_w2 = (const float*)d_in[14];
    const float* out_b2 = (const float*)d_in[15];
    float* out = (float*)d_out;

    cudaFuncSetAttribute(recurrent_kernel,
                         cudaFuncAttributeMaxDynamicSharedMemorySize, SMEM_BYTES);

    precompute_kernel<<<dim3(NB, 4), 256>>>(qseq, emb, keym, vu_w1, vu_b1);
    recurrent_kernel<<<NB, T, SMEM_BYTES>>>(qseq, emb, vu_w1, vu_w2, vu_b2,
                                            er_w, er_b, ad_w, ad_b,
                                            out_w1, out_b1, out_w2, out_b2, out);
}

// round 3
// speedup vs baseline: 2.6707x; 2.6707x over previous
#include <cuda_runtime.h>
#include <cstdint>
#include <math.h>

#define NB 128   // batch
#define NS 100   // seq len
#define NM 50    // memory slots
#define ND 128   // dim
#define T  256   // threads per CTA (recurrent kernel)

#define NROW (NB * NS)     // 12800 (b,s) rows
#define RPB  32            // rows per precompute block
#define KS   132           // padded key row stride (bank-conflict-free)

// Scratch for precomputed attention weights and qe@W1b+b1
__device__ float g_attn[NB * NS * NM];
__device__ float g_q1[NB * NS * ND];

// ---------------------------------------------------------------------------
// K1 (rewritten): tiled batched precompute.
// grid = NROW/RPB = 400 blocks, 256 threads. Per block: 32 rows.
//   smem: key (padded), w1b, b1, 32 gathered qe rows, ids.
//   logits+softmax: warp per 4 rows, lane per m (and m+32).
//   q1 GEMM: thread = 4 rows x 4 cols register tile.
// ---------------------------------------------------------------------------
// smem float layout
#define P_KEY  0
#define P_W1B  (NM * KS)                    // 6600
#define P_QE   (P_W1B + ND * ND)            // 22984
#define P_B1   (P_QE + RPB * ND)            // 27080
#define P_IDS  (P_B1 + ND)                  // 27208 (ints)
#define P_TOTF (P_IDS + RPB)
#define PRE_SMEM_BYTES (P_TOTF * 4)

__global__ __launch_bounds__(256, 1)
void precompute_kernel(const int* __restrict__ qseq,
                       const float* __restrict__ emb,
                       const float* __restrict__ keym,
                       const float* __restrict__ vu_w1,
                       const float* __restrict__ vu_b1) {
    extern __shared__ float ps[];
    float* sKey = ps + P_KEY;
    float* sW1b = ps + P_W1B;
    float* sQe  = ps + P_QE;
    float* sB1  = ps + P_B1;
    int*   sIds = (int*)(ps + P_IDS);

    const int t  = threadIdx.x;
    const int r0 = blockIdx.x * RPB;

    // ids for the 32 rows
    if (t < RPB) sIds[t] = qseq[r0 + t];

    // key matrix into padded smem
    for (int i = t; i < NM * ND / 4; i += 256) {
        const int m = i / 32, c4 = i % 32;           // 32 float4 per row
        *(float4*)(sKey + m * KS + c4 * 4) = ((const float4*)keym)[i];
    }
    // w1b (rows 128..255 of vu_w1)
    {
        const float4* src = (const float4*)(vu_w1 + ND * ND);
        for (int i = t; i < ND * ND / 4; i += 256) ((float4*)sW1b)[i] = src[i];
    }
    if (t < ND) sB1[t] = vu_b1[t];
    __syncthreads();

    // gather 32 qe rows (coalesced float4 per row)
    for (int i = t; i < RPB * 32; i += 256) {
        const int row = i >> 5, c4 = i & 31;
        const float4* src = (const float4*)(emb + (size_t)sIds[row] * ND);
        *(float4*)(sQe + row * ND + c4 * 4) = src[c4];
    }
    __syncthreads();

    // ---- logits + softmax: warp wid handles rows wid*4..+3; lane = m ----
    {
        const int wid = t >> 5, lid = t & 31;
        const int mB = (lid < NM - 32) ? lid + 32 : lid;   // clamp (dup discarded)
        float acc0[4] = {0, 0, 0, 0}, acc1[4] = {0, 0, 0, 0};
        const float* kA = sKey + lid * KS;
        const float* kB = sKey + mB * KS;
#pragma unroll
        for (int k4 = 0; k4 < 32; k4++) {
            const float4 a = *(const float4*)(kA + k4 * 4);
            const float4 b = *(const float4*)(kB + k4 * 4);
#pragma unroll
            for (int r = 0; r < 4; r++) {
                const float4 q = *(const float4*)(sQe + (wid * 4 + r) * ND + k4 * 4);
                acc0[r] = fmaf(q.x, a.x, fmaf(q.y, a.y, fmaf(q.z, a.z, fmaf(q.w, a.w, acc0[r]))));
                acc1[r] = fmaf(q.x, b.x, fmaf(q.y, b.y, fmaf(q.z, b.z, fmaf(q.w, b.w, acc1[r]))));
            }
        }
        const bool hasB = (lid < NM - 32);
#pragma unroll
        for (int r = 0; r < 4; r++) {
            float v0 = acc0[r];
            float v1 = hasB ? acc1[r] : -1e30f;
            float mx = fmaxf(v0, v1);
#pragma unroll
            for (int o = 16; o; o >>= 1) mx = fmaxf(mx, __shfl_xor_sync(0xffffffffu, mx, o));
            float e0 = __expf(v0 - mx);
            float e1 = hasB ? __expf(v1 - mx) : 0.f;
            float sum = e0 + e1;
#pragma unroll
            for (int o = 16; o; o >>= 1) sum += __shfl_xor_sync(0xffffffffu, sum, o);
            const float inv = 1.f / sum;
            float* dst = g_attn + (size_t)(r0 + wid * 4 + r) * NM;
            dst[lid] = e0 * inv;
            if (hasB) dst[lid + 32] = e1 * inv;
        }
    }

    // ---- q1 = qe @ w1b + b1 : thread = (rg: 4 rows) x (cg: 4 cols) ----
    {
        const int cg = t & 31;            // col4 = cg*4
        const int rg = t >> 5;            // rows rg*4..+3
        float4 acc[4] = {{0,0,0,0},{0,0,0,0},{0,0,0,0},{0,0,0,0}};
#pragma unroll 8
        for (int k4 = 0; k4 < 32; k4++) {
            const float4 w0 = *(const float4*)(sW1b + (k4 * 4 + 0) * ND + cg * 4);
            const float4 w1 = *(const float4*)(sW1b + (k4 * 4 + 1) * ND + cg * 4);
            const float4 w2 = *(const float4*)(sW1b + (k4 * 4 + 2) * ND + cg * 4);
            const float4 w3 = *(const float4*)(sW1b + (k4 * 4 + 3) * ND + cg * 4);
#pragma unroll
            for (int r = 0; r < 4; r++) {
                const float4 q = *(const float4*)(sQe + (rg * 4 + r) * ND + k4 * 4);
                acc[r].x = fmaf(q.x, w0.x, fmaf(q.y, w1.x, fmaf(q.z, w2.x, fmaf(q.w, w3.x, acc[r].x))));
                acc[r].y = fmaf(q.x, w0.y, fmaf(q.y, w1.y, fmaf(q.z, w2.y, fmaf(q.w, w3.y, acc[r].y))));
                acc[r].z = fmaf(q.x, w0.z, fmaf(q.y, w1.z, fmaf(q.z, w2.z, fmaf(q.w, w3.z, acc[r].z))));
                acc[r].w = fmaf(q.x, w0.w, fmaf(q.y, w1.w, fmaf(q.z, w2.w, fmaf(q.w, w3.w, acc[r].w))));
            }
        }
        const float4 b4 = *(const float4*)(sB1 + cg * 4);
#pragma unroll
        for (int r = 0; r < 4; r++) {
            float4 o = acc[r];
            o.x += b4.x; o.y += b4.y; o.z += b4.z; o.w += b4.w;
            *(float4*)(g_q1 + (size_t)(r0 + rg * 4 + r) * ND + cg * 4) = o;
        }
    }
}

// ---------------------------------------------------------------------------
// K2: persistent recurrent kernel — one CTA per batch element.
// W1a, W2 in smem (fp32); [er_w | ad_w] in registers (128 fp32/thread);
// v state in smem; the v update is fused with the NEXT step's read.
// ---------------------------------------------------------------------------
// smem layout (in floats)
#define SM_W1   0
#define SM_W2   16384
#define SM_V    32768          // 50*128
#define SM_ATTN 39168          // 100*50
#define SM_P    44168          // 4*256 reduction scratch
#define SM_READ 45192
#define SM_H    45320
#define SM_UP   45448
#define SM_E    45576
#define SM_A    45704
#define SM_TOTF 45832
#define SMEM_BYTES (SM_TOTF * 4)

__global__ __launch_bounds__(T, 1)
void recurrent_kernel(const int* __restrict__ qseq,
                      const float* __restrict__ emb,
                      const float* __restrict__ vu_w1,
                      const float* __restrict__ vu_w2,
                      const float* __restrict__ vu_b2,
                      const float* __restrict__ er_w,
                      const float* __restrict__ er_b,
                      const float* __restrict__ ad_w,
                      const float* __restrict__ ad_b,
                      const float* __restrict__ out_w1,
                      const float* __restrict__ out_b1,
                      const float* __restrict__ out_w2,
                      const float* __restrict__ out_b2,
                      float* __restrict__ out) {
    extern __shared__ float sm[];
    float* sW1   = sm + SM_W1;
    float* sW2   = sm + SM_W2;
    float* sV    = sm + SM_V;
    float* sAttn = sm + SM_ATTN;
    float* sP    = sm + SM_P;
    float* sRead = sm + SM_READ;
    float* sH    = sm + SM_H;
    float* sUp   = sm + SM_UP;
    float* sE    = sm + SM_E;
    float* sA    = sm + SM_A;

    const int b = blockIdx.x;
    const int t = threadIdx.x;

    // ---- load weights / init state ----
    for (int i = t; i < ND * ND; i += T) { sW1[i] = vu_w1[i]; sW2[i] = vu_w2[i]; }
    for (int i = t; i < NM * ND; i += T) sV[i] = 0.f;
    for (int i = t; i < NS * NM; i += T) sAttn[i] = g_attn[b * NS * NM + i];
    if (t < ND) sRead[t] = 0.f;

    // [er_w | ad_w] into registers: thread owns 4 outputs (jq) x 32 k (ks)
    const int jq = t & 63;       // output quad index over 256 combined outputs
    const int ks = t >> 6;       // k slice (4 slices of 32)
    float ea[128];
    {
        const float* src = (jq < 32) ? (er_w + jq * 4) : (ad_w + (jq - 32) * 4);
#pragma unroll
        for (int kk = 0; kk < 32; kk++) {
            const float4 w4 = *(const float4*)(src + (ks * 32 + kk) * ND);
            ea[kk * 4 + 0] = w4.x; ea[kk * 4 + 1] = w4.y;
            ea[kk * 4 + 2] = w4.z; ea[kk * 4 + 3] = w4.w;
        }
    }
    const float biasO = (t < ND) ? er_b[t] : ad_b[t - ND];  // for C reduce, output t
    const float b2r   = (t < ND) ? vu_b2[t] : 0.f;

    // stage mappings
    const int j4 = (t & 31) * 4;   // GEMV1/2: 4 adjacent outputs
    const int kg = t >> 5;         // GEMV1/2: 8 k-groups of 16 (== warp id)
    const int d2 = t & 63;         // D stage: d pair
    const int mg = t >> 6;         // D stage: 4 m-groups
    const int mstart = (mg < 2) ? mg * 13 : 26 + (mg - 2) * 12;
    const int mcount = (mg < 2) ? 13 : 12;

    __syncthreads();

    const float* q1b = g_q1 + b * NS * ND;

    for (int s = 0; s < NS; s++) {
        // prefetch this step's q1 (consumed in A-reduce)
        float q1v = 0.f;
        if (t < ND) q1v = q1b[s * ND + t];

        // ---- A: h = tanh(read @ W1a + q1) ----
        {
            float4 acc = {0.f, 0.f, 0.f, 0.f};
            const float4* xr = (const float4*)(sRead + kg * 16);
#pragma unroll
            for (int k4 = 0; k4 < 4; k4++) {
                const float4 x = xr[k4];
                const float* wb = sW1 + (kg * 16 + k4 * 4) * ND + j4;
                const float4 w0 = *(const float4*)(wb);
                const float4 w1 = *(const float4*)(wb + ND);
                const float4 w2 = *(const float4*)(wb + 2 * ND);
                const float4 w3 = *(const float4*)(wb + 3 * ND);
                acc.x = fmaf(x.x, w0.x, fmaf(x.y, w1.x, fmaf(x.z, w2.x, fmaf(x.w, w3.x, acc.x))));
                acc.y = fmaf(x.x, w0.y, fmaf(x.y, w1.y, fmaf(x.z, w2.y, fmaf(x.w, w3.y, acc.y))));
                acc.z = fmaf(x.x, w0.z, fmaf(x.y, w1.z, fmaf(x.z, w2.z, fmaf(x.w, w3.z, acc.z))));
                acc.w = fmaf(x.x, w0.w, fmaf(x.y, w1.w, fmaf(x.z, w2.w, fmaf(x.w, w3.w, acc.w))));
            }
            *(float4*)(sP + kg * ND + j4) = acc;
        }
        __syncthreads();
        if (t < ND) {
            float v = q1v;
#pragma unroll
            for (int g = 0; g < 8; g++) v += sP[g * ND + t];
            sH[t] = tanhf(v);
        }
        __syncthreads();

        // ---- B: up = h @ W2 + b2 ----
        {
            float4 acc = {0.f, 0.f, 0.f, 0.f};
            const float4* xr = (const float4*)(sH + kg * 16);
#pragma unroll
            for (int k4 = 0; k4 < 4; k4++) {
                const float4 x = xr[k4];
                const float* wb = sW2 + (kg * 16 + k4 * 4) * ND + j4;
                const float4 w0 = *(const float4*)(wb);
                const float4 w1 = *(const float4*)(wb + ND);
                const float4 w2 = *(const float4*)(wb + 2 * ND);
                const float4 w3 = *(const float4*)(wb + 3 * ND);
                acc.x = fmaf(x.x, w0.x, fmaf(x.y, w1.x, fmaf(x.z, w2.x, fmaf(x.w, w3.x, acc.x))));
                acc.y = fmaf(x.x, w0.y, fmaf(x.y, w1.y, fmaf(x.z, w2.y, fmaf(x.w, w3.y, acc.y))));
                acc.z = fmaf(x.x, w0.z, fmaf(x.y, w1.z, fmaf(x.z, w2.z, fmaf(x.w, w3.z, acc.z))));
                acc.w = fmaf(x.x, w0.w, fmaf(x.y, w1.w, fmaf(x.z, w2.w, fmaf(x.w, w3.w, acc.w))));
            }
            *(float4*)(sP + kg * ND + j4) = acc;
        }
        __syncthreads();
        if (t < ND) {
            float v = b2r;
#pragma unroll
            for (int g = 0; g < 8; g++) v += sP[g * ND + t];
            sUp[t] = v;
        }
        __syncthreads();

        // ---- C: e = sigmoid(up@er_w + er_b), a = tanh(up@ad_w + ad_b) (regs) ----
        {
            float4 acc = {0.f, 0.f, 0.f, 0.f};
            const float4* xr = (const float4*)(sUp + ks * 32);
#pragma unroll
            for (int k4 = 0; k4 < 8; k4++) {
                const float4 x = xr[k4];
                const float* e0 = ea + k4 * 16;
                acc.x = fmaf(x.x, e0[0],  fmaf(x.y, e0[4],  fmaf(x.z, e0[8],  fmaf(x.w, e0[12], acc.x))));
                acc.y = fmaf(x.x, e0[1],  fmaf(x.y, e0[5],  fmaf(x.z, e0[9],  fmaf(x.w, e0[13], acc.y))));
                acc.z = fmaf(x.x, e0[2],  fmaf(x.y, e0[6],  fmaf(x.z, e0[10], fmaf(x.w, e0[14], acc.z))));
                acc.w = fmaf(x.x, e0[3],  fmaf(x.y, e0[7],  fmaf(x.z, e0[11], fmaf(x.w, e0[15], acc.w))));
            }
            *(float4*)(sP + ks * 256 + jq * 4) = acc;
        }
        __syncthreads();
        {
            float v = biasO;
#pragma unroll
            for (int g = 0; g < 4; g++) v += sP[g * 256 + t];
            if (t < ND) sE[t] = 1.f / (1.f + __expf(-v));
            else        sA[t - ND] = tanhf(v);
        }
        __syncthreads();

        // ---- D: v <- v + w_t*(a - e*v), fused with next read = w_{t+1} . v ----
        {
            const float* wrow = sAttn + s * NM;
            const float* wnxt = sAttn + ((s + 1 < NS) ? s + 1 : NS - 1) * NM;
            const float ex = sE[d2 * 2], ey = sE[d2 * 2 + 1];
            const float ax = sA[d2 * 2], ay = sA[d2 * 2 + 1];
            float rpx = 0.f, rpy = 0.f;
#pragma unroll
            for (int mi = 0; mi < 13; mi++) {
                if (mi < mcount) {
                    const int m = mstart + mi;
                    const float wt = wrow[m];
                    const float wn = wnxt[m];
                    float2 v2 = *(float2*)(sV + m * ND + d2 * 2);
                    const float fx = fmaf(-ex, v2.x, ax);
                    const float fy = fmaf(-ey, v2.y, ay);
                    v2.x = fmaf(wt, fx, v2.x);
                    v2.y = fmaf(wt, fy, v2.y);
                    *(float2*)(sV + m * ND + d2 * 2) = v2;
                    rpx = fmaf(wn, v2.x, rpx);
                    rpy = fmaf(wn, v2.y, rpy);
                }
            }
            sP[mg * ND + d2 * 2]     = rpx;
            sP[mg * ND + d2 * 2 + 1] = rpy;
        }
        __syncthreads();
        if (t < ND) {
            float v = 0.f;
#pragma unroll
            for (int g = 0; g < 4; g++) v += sP[g * ND + t];
            sRead[t] = v;
        }
        __syncthreads();
    }

    // ---- output head: pred = sigmoid(relu([read, qe_last] @ out_w1 + b1) @ out_w2 + b2)
    {
        const int qi = qseq[b * NS + (NS - 1)];
        if (t < ND) sUp[t] = emb[qi * ND + t];   // qe_last
    }
    __syncthreads();
    {
        // 256-k GEMV: kg in 0..7 owns 32 k; k<128 from sRead, k>=128 from sUp
        const float* pin = (kg < 4) ? sRead : (sUp - ND);
        float4 acc = {0.f, 0.f, 0.f, 0.f};
#pragma unroll
        for (int i = 0; i < 32; i++) {
            const int k = kg * 32 + i;
            const float x = pin[k];
            const float4 w = *(const float4*)(out_w1 + k * ND + j4);
            acc.x = fmaf(x, w.x, acc.x);
            acc.y = fmaf(x, w.y, acc.y);
            acc.z = fmaf(x, w.z, acc.z);
            acc.w = fmaf(x, w.w, acc.w);
        }
        *(float4*)(sP + kg * ND + j4) = acc;
    }
    __syncthreads();
    if (t < ND) {
        float v = out_b1[t];
#pragma unroll
        for (int g = 0; g < 8; g++) v += sP[g * ND + t];
        sH[t] = fmaxf(v, 0.f) * out_w2[t];
    }
    __syncthreads();
    if (t < 32) {
        float v = sH[t] + sH[t + 32] + sH[t + 64] + sH[t + 96];
#pragma unroll
        for (int o = 16; o; o >>= 1) v += __shfl_xor_sync(0xffffffffu, v, o);
        if (t == 0) out[b] = 1.f / (1.f + __expf(-(v + out_b2[0])));
    }
}

// ---------------------------------------------------------------------------
extern "C" void kernel_launch(void* const* d_in, const int* in_sizes, int n_in,
                              void* d_out, int out_size) {
    const int*   qseq   = (const int*)  d_in[0];
    // d_in[1] = answer_seq (unused by reference)
    const float* emb    = (const float*)d_in[2];
    const float* keym   = (const float*)d_in[3];
    const float* vu_w1  = (const float*)d_in[4];
    const float* vu_b1  = (const float*)d_in[5];
    const float* vu_w2  = (const float*)d_in[6];
    const float* vu_b2  = (const float*)d_in[7];
    const float* er_w   = (const float*)d_in[8];
    const float* er_b   = (const float*)d_in[9];
    const float* ad_w   = (const float*)d_in[10];
    const float* ad_b   = (const float*)d_in[11];
    const float* out_w1 = (const float*)d_in[12];
    const float* out_b1 = (const float*)d_in[13];
    const float* out_w2 = (const float*)d_in[14];
    const float* out_b2 = (const float*)d_in[15];
    float* out = (float*)d_out;

    cudaFuncSetAttribute(precompute_kernel,
                         cudaFuncAttributeMaxDynamicSharedMemorySize, PRE_SMEM_BYTES);
    cudaFuncSetAttribute(recurrent_kernel,
                         cudaFuncAttributeMaxDynamicSharedMemorySize, SMEM_BYTES);

    precompute_kernel<<<NROW / RPB, 256, PRE_SMEM_BYTES>>>(qseq, emb, keym, vu_w1, vu_b1);
    recurrent_kernel<<<NB, T, SMEM_BYTES>>>(qseq, emb, vu_w1, vu_w2, vu_b2,
                                            er_w, er_b, ad_w, ad_b,
                                            out_w1, out_b1, out_w2, out_b2, out);
}